// round 2
// baseline (speedup 1.0000x reference)
#include <cuda_runtime.h>
#include <cstdint>

// ---------------------------------------------------------------------------
// Problem constants
// ---------------------------------------------------------------------------
#define BB   2
#define LL   2048
#define DM   512
#define HH   8
#define KT   5            // kernel taps
#define HW   64           // head width
#define MTOT (BB*LL)                  // 4096 rows
#define NQ_  (DM)                     // 512 q rows in W_all
#define NKV_ (HH*KT*HW)               // 2560 rows each for k and v
#define NTOT (NQ_ + 2*NKV_)           // 5632
#define KBASE (NQ_)                   // 512
#define VBASE (NQ_ + NKV_)            // 3072

// ---------------------------------------------------------------------------
// Device scratch (allowed: __device__ globals, no runtime allocation)
// ---------------------------------------------------------------------------
__device__ float g_Xr  [(size_t)MTOT * DM];       //  8.4 MB  tf32-rounded x
__device__ float g_Wall[(size_t)NTOT * DM];       // 11.5 MB  tf32-rounded [q;k;v] weights
__device__ float g_OWr [(size_t)DM * DM];         //  1.0 MB  tf32-rounded o_w
__device__ float g_PROJ[(size_t)MTOT * NTOT];     // 92.3 MB  projections
__device__ float g_ATTN[(size_t)MTOT * DM];       //  8.4 MB  tf32-rounded attn output

// ---------------------------------------------------------------------------
// Helpers
// ---------------------------------------------------------------------------
__device__ __forceinline__ float to_tf32(float x) {
    uint32_t u = __float_as_uint(x), r;
    asm("cvt.rna.tf32.f32 %0, %1;" : "=r"(r) : "r"(u));
    return __uint_as_float(r);
}

__device__ __forceinline__ void mma_tf32(float d[4], const uint32_t a[4], const uint32_t b[2]) {
    asm volatile(
        "mma.sync.aligned.m16n8k8.row.col.f32.tf32.tf32.f32 "
        "{%0,%1,%2,%3}, {%4,%5,%6,%7}, {%8,%9}, {%0,%1,%2,%3};\n"
        : "+f"(d[0]), "+f"(d[1]), "+f"(d[2]), "+f"(d[3])
        : "r"(a[0]), "r"(a[1]), "r"(a[2]), "r"(a[3]), "r"(b[0]), "r"(b[1]));
}

#define CP_ASYNC16(smem32, gptr) \
    asm volatile("cp.async.cg.shared.global [%0], [%1], 16;\n" :: "r"(smem32), "l"(gptr))

// ---------------------------------------------------------------------------
// K0: round x -> g_Xr, assemble+round W_all (concat q_w,k_w,v_w), round o_w
// ---------------------------------------------------------------------------
#define PREP_TOT (MTOT*DM + NTOT*DM + DM*DM)   // 5,242,880

__global__ void prep_kernel(const float* __restrict__ x,
                            const float* __restrict__ qw,
                            const float* __restrict__ kw,
                            const float* __restrict__ vw,
                            const float* __restrict__ ow) {
    const int NX  = MTOT * DM;        // 2097152
    const int NQW = DM * DM;          // 262144
    const int NKW = NKV_ * DM;        // 1310720
    const int NW  = NQW + 2 * NKW;    // 2883584
    int i = blockIdx.x * blockDim.x + threadIdx.x;
    if (i >= PREP_TOT) return;
    if (i < NX) {
        g_Xr[i] = to_tf32(x[i]);
    } else {
        int j = i - NX;
        if (j < NW) {
            float v;
            if (j < NQW)            v = qw[j];
            else if (j < NQW + NKW) v = kw[j - NQW];
            else                    v = vw[j - NQW - NKW];
            g_Wall[j] = to_tf32(v);
        } else {
            g_OWr[j - NW] = to_tf32(ow[j - NW]);
        }
    }
}

// ---------------------------------------------------------------------------
// GEMM: C[M][N] = A[M][K] * B[N][K]^T (+bias[n]),  tf32 mma.sync, fp32 accum
// BM=128, BN=128, BK=16, 256 threads (8 warps, 2x4), warp tile 64x32
// ---------------------------------------------------------------------------
#define BM 128
#define BN 128
#define BK 16
#define SK 20      // smem row stride (pad: conflict-free LDS pattern)

template <bool HAS_BIAS>
__global__ __launch_bounds__(256) void gemm_tf32(
    const float* __restrict__ A, const float* __restrict__ B,
    float* __restrict__ C, int M, int N, int Kdim,
    const float* __restrict__ bias)
{
    __shared__ float As[2][BM * SK];
    __shared__ float Bs[2][BN * SK];

    const int n0  = blockIdx.x * BN;
    const int m0  = blockIdx.y * BM;
    const int tid = threadIdx.x;
    const int warp = tid >> 5, lane = tid & 31;
    const int wm = (warp >> 2) * 64;   // 0 or 64
    const int wn = (warp & 3) * 32;    // 0,32,64,96
    const int g  = lane >> 2, t = lane & 3;

    float acc[4][4][4];
    #pragma unroll
    for (int mt = 0; mt < 4; mt++)
        #pragma unroll
        for (int nt = 0; nt < 4; nt++)
            #pragma unroll
            for (int i = 0; i < 4; i++) acc[mt][nt][i] = 0.f;

    const float* Ab = A + (size_t)m0 * Kdim;
    const float* Bb = B + (size_t)n0 * Kdim;

    auto load_stage = [&](int s, int k0) {
        #pragma unroll
        for (int it = 0; it < 2; ++it) {
            int idx = tid + 256 * it;
            int row = idx >> 2;
            int c   = (idx & 3) * 4;
            uint32_t sa = (uint32_t)__cvta_generic_to_shared(&As[s][row * SK + c]);
            CP_ASYNC16(sa, Ab + (size_t)row * Kdim + k0 + c);
            uint32_t sb = (uint32_t)__cvta_generic_to_shared(&Bs[s][row * SK + c]);
            CP_ASYNC16(sb, Bb + (size_t)row * Kdim + k0 + c);
        }
        asm volatile("cp.async.commit_group;\n" ::);
    };

    const int NKt = Kdim / BK;
    load_stage(0, 0);

    for (int kt = 0; kt < NKt; ++kt) {
        if (kt + 1 < NKt) {
            load_stage((kt + 1) & 1, (kt + 1) * BK);
            asm volatile("cp.async.wait_group 1;\n" ::);
        } else {
            asm volatile("cp.async.wait_group 0;\n" ::);
        }
        __syncthreads();

        const float* as = As[kt & 1];
        const float* bs = Bs[kt & 1];

        #pragma unroll
        for (int ks = 0; ks < 2; ++ks) {
            const int kb = ks * 8;
            uint32_t af[4][4], bf[4][2];
            #pragma unroll
            for (int mt = 0; mt < 4; mt++) {
                int r = wm + mt * 16 + g;
                af[mt][0] = __float_as_uint(as[(r    ) * SK + kb + t    ]);
                af[mt][1] = __float_as_uint(as[(r + 8) * SK + kb + t    ]);
                af[mt][2] = __float_as_uint(as[(r    ) * SK + kb + t + 4]);
                af[mt][3] = __float_as_uint(as[(r + 8) * SK + kb + t + 4]);
            }
            #pragma unroll
            for (int nt = 0; nt < 4; nt++) {
                int n = wn + nt * 8 + g;
                bf[nt][0] = __float_as_uint(bs[n * SK + kb + t    ]);
                bf[nt][1] = __float_as_uint(bs[n * SK + kb + t + 4]);
            }
            #pragma unroll
            for (int mt = 0; mt < 4; mt++)
                #pragma unroll
                for (int nt = 0; nt < 4; nt++)
                    mma_tf32(acc[mt][nt], af[mt], bf[nt]);
        }
        __syncthreads();
    }

    // Epilogue: c-frag layout c0:(g,2t) c1:(g,2t+1) c2:(g+8,2t) c3:(g+8,2t+1)
    #pragma unroll
    for (int mt = 0; mt < 4; mt++) {
        int r = m0 + wm + mt * 16 + g;
        #pragma unroll
        for (int nt = 0; nt < 4; nt++) {
            int c = n0 + wn + nt * 8 + 2 * t;
            float b0 = 0.f, b1 = 0.f;
            if (HAS_BIAS) { b0 = bias[c]; b1 = bias[c + 1]; }
            *(float2*)&C[(size_t)(r    ) * N + c] = make_float2(acc[mt][nt][0] + b0, acc[mt][nt][1] + b1);
            *(float2*)&C[(size_t)(r + 8) * N + c] = make_float2(acc[mt][nt][2] + b0, acc[mt][nt][3] + b1);
        }
    }
}

// ---------------------------------------------------------------------------
// K2: attention. One warp per (b,l,h). 5-tap gather from PROJ, softmax,
// weighted V sum, /sqrt(64), tf32-round into g_ATTN.
// Out-of-range taps: content is zero => k/v collapse to their biases.
// ---------------------------------------------------------------------------
__global__ __launch_bounds__(256) void attn_kernel(const float* __restrict__ qb,
                                                   const float* __restrict__ kb,
                                                   const float* __restrict__ vb) {
    int w    = (blockIdx.x * blockDim.x + threadIdx.x) >> 5;
    int lane = threadIdx.x & 31;
    if (w >= MTOT * HH) return;

    int h   = w & 7;
    int row = w >> 3;                 // = b*LL + l
    int l   = row & (LL - 1);
    int b   = row >> 11;
    int d   = 1 << (h & 3);           // dilations {1,2,4,8,1,2,4,8}

    const float* P = g_PROJ;
    size_t rq = (size_t)row * NTOT;
    int qoff = h * HW;
    float q0 = P[rq + qoff + lane]      + qb[qoff + lane];
    float q1 = P[rq + qoff + lane + 32] + qb[qoff + lane + 32];

    float lg[KT], v0[KT], v1[KT];
    #pragma unroll
    for (int kk = 0; kk < KT; ++kk) {
        int sl   = l + (kk - 2) * d;
        int kidx = (h * KT + kk) * HW;
        float kv0, kv1;
        if (sl >= 0 && sl < LL) {
            size_t rr = (size_t)(b * LL + sl) * NTOT;
            kv0    = P[rr + KBASE + kidx + lane]      + kb[kidx + lane];
            kv1    = P[rr + KBASE + kidx + lane + 32] + kb[kidx + lane + 32];
            v0[kk] = P[rr + VBASE + kidx + lane]      + vb[kidx + lane];
            v1[kk] = P[rr + VBASE + kidx + lane + 32] + vb[kidx + lane + 32];
        } else {
            kv0    = kb[kidx + lane];      kv1    = kb[kidx + lane + 32];
            v0[kk] = vb[kidx + lane];      v1[kk] = vb[kidx + lane + 32];
        }
        float p = q0 * kv0 + q1 * kv1;
        #pragma unroll
        for (int s = 16; s > 0; s >>= 1) p += __shfl_xor_sync(0xffffffffu, p, s);
        lg[kk] = p;
    }

    float mx = lg[0];
    #pragma unroll
    for (int kk = 1; kk < KT; ++kk) mx = fmaxf(mx, lg[kk]);
    float e[KT], se = 0.f;
    #pragma unroll
    for (int kk = 0; kk < KT; ++kk) { e[kk] = __expf(lg[kk] - mx); se += e[kk]; }
    float inv = 1.f / se;

    float a0 = 0.f, a1 = 0.f;
    #pragma unroll
    for (int kk = 0; kk < KT; ++kk) { a0 += e[kk] * v0[kk]; a1 += e[kk] * v1[kk]; }
    a0 *= inv * 0.125f;   // / sqrt(HEAD_W)
    a1 *= inv * 0.125f;

    g_ATTN[(size_t)row * DM + qoff + lane]      = to_tf32(a0);
    g_ATTN[(size_t)row * DM + qoff + lane + 32] = to_tf32(a1);
}

// ---------------------------------------------------------------------------
// Launch
// ---------------------------------------------------------------------------
extern "C" void kernel_launch(void* const* d_in, const int* in_sizes, int n_in,
                              void* d_out, int out_size) {
    const float* x   = (const float*)d_in[0];
    const float* q_w = (const float*)d_in[1];
    const float* q_b = (const float*)d_in[2];
    const float* k_w = (const float*)d_in[3];
    const float* k_b = (const float*)d_in[4];
    const float* v_w = (const float*)d_in[5];
    const float* v_b = (const float*)d_in[6];
    const float* o_w = (const float*)d_in[7];
    const float* o_b = (const float*)d_in[8];

    float *Xr, *Wall, *OWr, *PROJ, *ATTN;
    cudaGetSymbolAddress((void**)&Xr,   g_Xr);
    cudaGetSymbolAddress((void**)&Wall, g_Wall);
    cudaGetSymbolAddress((void**)&OWr,  g_OWr);
    cudaGetSymbolAddress((void**)&PROJ, g_PROJ);
    cudaGetSymbolAddress((void**)&ATTN, g_ATTN);

    // K0: prep (round + assemble)
    prep_kernel<<<(PREP_TOT + 255) / 256, 256>>>(x, q_w, k_w, v_w, o_w);

    // K1: PROJ[4096,5632] = Xr @ Wall^T
    gemm_tf32<false><<<dim3(NTOT / BN, MTOT / BM), 256>>>(Xr, Wall, PROJ, MTOT, NTOT, DM, nullptr);

    // K2: attention -> ATTN[4096,512]
    attn_kernel<<<(MTOT * HH * 32) / 256, 256>>>(q_b, k_b, v_b);

    // K3: OUT = ATTN @ OWr^T + o_b
    gemm_tf32<true><<<dim3(DM / BN, MTOT / BM), 256>>>(ATTN, OWr, (float*)d_out, MTOT, DM, DM, o_b);
}